// round 14
// baseline (speedup 1.0000x reference)
#include <cuda_runtime.h>
#include <cuda_bf16.h>
#include <cstdint>
#include <math.h>

#define BATCH 8
#define CIN   256
#define CI    128
#define NSP   6272   // 8*28*28
#define MSP   1568   // 8*14*14

// ---- scratch (static device arrays; allocation-free) ----
__device__ float g_Tphi[BATCH * NSP * CI];
__device__ float g_Tg  [BATCH * NSP * CI];
__device__ __nv_bfloat16 g_Qh[BATCH * NSP * CI];
__device__ __nv_bfloat16 g_Ql[BATCH * NSP * CI];
__device__ __nv_bfloat16 g_Kh[BATCH * MSP * CI];
__device__ __nv_bfloat16 g_Kl[BATCH * MSP * CI];
__device__ __nv_bfloat16 g_Vh[BATCH * MSP * CI];
__device__ __nv_bfloat16 g_Vl[BATCH * MSP * CI];
__device__ __nv_bfloat16 g_Yh[BATCH * NSP * CI];
__device__ __nv_bfloat16 g_Yl[BATCH * NSP * CI];
// pre-split weights
__device__ __nv_bfloat16 g_PWh[3 * 128 * 256];
__device__ __nv_bfloat16 g_PWl[3 * 128 * 256];
__device__ __nv_bfloat16 g_OWh[256 * 128];
__device__ __nv_bfloat16 g_OWl[256 * 128];

__device__ __forceinline__ uint32_t smem_u32(const void* p) {
    uint32_t a;
    asm("{ .reg .u64 t; cvta.to.shared.u64 t, %1; cvt.u32.u64 %0, t; }"
        : "=r"(a) : "l"(p));
    return a;
}

// ---- mma.sync / ldmatrix / cp.async (all sm_80 baseline ISA) ----
__device__ __forceinline__ void ldsm4(uint32_t (&r)[4], uint32_t addr) {
    asm volatile("ldmatrix.sync.aligned.m8n8.x4.shared.b16 {%0,%1,%2,%3}, [%4];"
        : "=r"(r[0]), "=r"(r[1]), "=r"(r[2]), "=r"(r[3]) : "r"(addr));
}
__device__ __forceinline__ void ldsm4t(uint32_t (&r)[4], uint32_t addr) {
    asm volatile("ldmatrix.sync.aligned.m8n8.x4.trans.shared.b16 {%0,%1,%2,%3}, [%4];"
        : "=r"(r[0]), "=r"(r[1]), "=r"(r[2]), "=r"(r[3]) : "r"(addr));
}
__device__ __forceinline__ void mma16816(float (&d)[4], const uint32_t (&a)[4],
                                         uint32_t b0, uint32_t b1) {
    asm volatile("mma.sync.aligned.m16n8k16.row.col.f32.bf16.bf16.f32 "
        "{%0,%1,%2,%3}, {%4,%5,%6,%7}, {%8,%9}, {%0,%1,%2,%3};"
        : "+f"(d[0]), "+f"(d[1]), "+f"(d[2]), "+f"(d[3])
        : "r"(a[0]), "r"(a[1]), "r"(a[2]), "r"(a[3]), "r"(b0), "r"(b1));
}
#define CP_ASYNC16(smem, gptr) \
    asm volatile("cp.async.cg.shared.global [%0], [%1], 16;" \
                 :: "r"(smem), "l"(gptr) : "memory")
#define CP_COMMIT() asm volatile("cp.async.commit_group;" ::: "memory")
#define CP_WAIT0()  asm volatile("cp.async.wait_group 0;" ::: "memory")
#define CP_WAIT1()  asm volatile("cp.async.wait_group 1;" ::: "memory")

// ============================================================
// Kernel 0: pre-split weights to bf16 hi/lo
// ============================================================
__global__ void prep_kernel(const float* __restrict__ th_w,
                            const float* __restrict__ ph_w,
                            const float* __restrict__ gw,
                            const float* __restrict__ Ww)
{
    const int i = blockIdx.x * blockDim.x + threadIdx.x;   // 0..131071
    const int PN = 128 * 256;
    float v; __nv_bfloat16 *dh, *dl;
    if (i < 3 * PN) {
        const int p = i / PN, o = i % PN;
        const float* s = (p == 0) ? th_w : (p == 1) ? ph_w : gw;
        v = s[o]; dh = g_PWh + i; dl = g_PWl + i;
    } else {
        const int o = i - 3 * PN;
        v = Ww[o]; dh = g_OWh + o; dl = g_OWl + o;
    }
    __nv_bfloat16 h = __float2bfloat16(v);
    *dh = h;
    *dl = __float2bfloat16(v - __bfloat162float(h));
}

// ============================================================
// Kernel 1: fused projections, split-bf16 mma.sync, cp.async double-buffered W.
// grid (49, 8), 256 threads. SMEM: Xh/Xl (139264) + 2 W buffers (2x36864).
// ============================================================
#define PX 136
#define PW 72
#define PS 136
#define PF 132
#define OFF_XL 69632
#define OFF_U  139264
#define WBUF   36864
#define W_LO   18432
#define PROJ_SMEM (139264 + 2 * 36864)   // 212992

__device__ __forceinline__ void proj_issueW(uint32_t sb,
        const __nv_bfloat16* __restrict__ wh,
        const __nv_bfloat16* __restrict__ wl,
        int chunk, int bufoff, int tid)
{
    const int cbase = chunk * 64;
    for (int i = tid; i < 1024; i += 256) {
        const int j = i >> 3, s = i & 7;
        const uint32_t d = sb + OFF_U + bufoff + j * 144 + s * 16;
        CP_ASYNC16(d,        wh + (size_t)j * CIN + cbase + s * 8);
        CP_ASYNC16(d + W_LO, wl + (size_t)j * CIN + cbase + s * 8);
    }
    CP_COMMIT();
}

__global__ __launch_bounds__(256) void proj_kernel(
    const float* __restrict__ x,
    const float* __restrict__ th_b, const float* __restrict__ ph_b,
    const float* __restrict__ gb)
{
    extern __shared__ __align__(16) char ps[];
    const int tid = threadIdx.x, lane = tid & 31, warp = tid >> 5;
    const int nb = blockIdx.x * 128, b = blockIdx.y;
    const uint32_t sb = smem_u32(ps);

    // prefetch p=0 chunk 0 while we split X
    proj_issueW(sb, g_PWh, g_PWl, 0, 0, tid);

    // ---- load + split X tile (256 c-rows x 128 n-cols) ----
    const float* xb = x + (size_t)b * CIN * NSP + nb;
    for (int i = tid; i < 256 * 32; i += 256) {
        const int c = i >> 5, n4 = (i & 31) << 2;
        float4 v = *(const float4*)(xb + (size_t)c * NSP + n4);
        __nv_bfloat162 h01 = __floats2bfloat162_rn(v.x, v.y);
        __nv_bfloat162 h23 = __floats2bfloat162_rn(v.z, v.w);
        *(__nv_bfloat162*)(ps + (c * PX + n4) * 2)     = h01;
        *(__nv_bfloat162*)(ps + (c * PX + n4) * 2 + 4) = h23;
        __nv_bfloat162 l01 = __floats2bfloat162_rn(v.x - __bfloat162float(h01.x),
                                                   v.y - __bfloat162float(h01.y));
        __nv_bfloat162 l23 = __floats2bfloat162_rn(v.z - __bfloat162float(h23.x),
                                                   v.w - __bfloat162float(h23.y));
        *(__nv_bfloat162*)(ps + OFF_XL + (c * PX + n4) * 2)     = l01;
        *(__nv_bfloat162*)(ps + OFF_XL + (c * PX + n4) * 2 + 4) = l23;
    }

    const uint32_t xRow = (lane & 7) + (((lane >> 3) & 1) << 3);
    const uint32_t aX = sb + (xRow * PX + ((lane >> 4) << 3)) * 2;
    const int j0 = warp * 16 + (lane >> 2), j1 = j0 + 8;

    for (int p = 0; p < 3; p++) {
        const __nv_bfloat16* wh = g_PWh + p * 32768;
        const __nv_bfloat16* wl = g_PWl + p * 32768;
        const float* bp = (p == 0) ? th_b : (p == 1) ? ph_b : gb;
        if (p > 0) proj_issueW(sb, wh, wl, 0, 0, tid);

        float D[16][4];
#pragma unroll
        for (int t = 0; t < 16; t++)
#pragma unroll
            for (int j = 0; j < 4; j++) D[t][j] = 0.f;

        for (int c = 0; c < 4; c++) {
            if (c < 3) proj_issueW(sb, wh, wl, c + 1, ((c + 1) & 1) * WBUF, tid);
            if (c < 3) { CP_WAIT1(); } else { CP_WAIT0(); }
            __syncthreads();
            const uint32_t aW = sb + OFF_U + (c & 1) * WBUF
                + ((warp * 16 + (lane & 15)) * PW + ((lane >> 4) << 3)) * 2;
#pragma unroll
            for (int kk2 = 0; kk2 < 4; kk2++) {
                uint32_t Ah[4], Al[4];
                ldsm4(Ah, aW + kk2 * 32);
                ldsm4(Al, aW + W_LO + kk2 * 32);
                const uint32_t xoff = (c * 4 + kk2) * (16 * PX * 2);
#pragma unroll
                for (int g = 0; g < 8; g++) {
                    uint32_t Bh[4], Bl[4];
                    ldsm4t(Bh, aX + xoff + g * 32);
                    ldsm4t(Bl, aX + OFF_XL + xoff + g * 32);
                    mma16816(D[2 * g],     Ah, Bh[0], Bh[1]);
                    mma16816(D[2 * g + 1], Ah, Bh[2], Bh[3]);
                    mma16816(D[2 * g],     Ah, Bl[0], Bl[1]);
                    mma16816(D[2 * g + 1], Ah, Bl[2], Bl[3]);
                    mma16816(D[2 * g],     Al, Bh[0], Bh[1]);
                    mma16816(D[2 * g + 1], Al, Bh[2], Bh[3]);
                }
            }
            __syncthreads();
        }

        const float bias0 = bp[j0], bias1 = bp[j1];
        if (p == 0) {
            // theta: split bf16 via staged transpose, two passes
            __nv_bfloat16* dsth = g_Qh + ((size_t)b * NSP + nb) * CI;
            __nv_bfloat16* dstl = g_Ql + ((size_t)b * NSP + nb) * CI;
#pragma unroll
            for (int t = 0; t < 16; t++) {
                const int n = t * 8 + (lane & 3) * 2;
                *(__nv_bfloat16*)(ps + OFF_U + (n * PS + j0) * 2)       = __float2bfloat16(D[t][0] + bias0);
                *(__nv_bfloat16*)(ps + OFF_U + ((n + 1) * PS + j0) * 2) = __float2bfloat16(D[t][1] + bias0);
                *(__nv_bfloat16*)(ps + OFF_U + (n * PS + j1) * 2)       = __float2bfloat16(D[t][2] + bias1);
                *(__nv_bfloat16*)(ps + OFF_U + ((n + 1) * PS + j1) * 2) = __float2bfloat16(D[t][3] + bias1);
            }
            __syncthreads();
            for (int i = tid; i < 128 * 16; i += 256) {
                const int n = i >> 4, j8 = (i & 15) << 3;
                *(uint4*)(dsth + (size_t)n * CI + j8) =
                    *(const uint4*)(ps + OFF_U + (n * PS + j8) * 2);
            }
            __syncthreads();
#pragma unroll
            for (int t = 0; t < 16; t++) {
                const int n = t * 8 + (lane & 3) * 2;
                const float v0 = D[t][0] + bias0, v1 = D[t][1] + bias0;
                const float v2 = D[t][2] + bias1, v3 = D[t][3] + bias1;
                *(__nv_bfloat16*)(ps + OFF_U + (n * PS + j0) * 2) =
                    __float2bfloat16(v0 - __bfloat162float(__float2bfloat16(v0)));
                *(__nv_bfloat16*)(ps + OFF_U + ((n + 1) * PS + j0) * 2) =
                    __float2bfloat16(v1 - __bfloat162float(__float2bfloat16(v1)));
                *(__nv_bfloat16*)(ps + OFF_U + (n * PS + j1) * 2) =
                    __float2bfloat16(v2 - __bfloat162float(__float2bfloat16(v2)));
                *(__nv_bfloat16*)(ps + OFF_U + ((n + 1) * PS + j1) * 2) =
                    __float2bfloat16(v3 - __bfloat162float(__float2bfloat16(v3)));
            }
            __syncthreads();
            for (int i = tid; i < 128 * 16; i += 256) {
                const int n = i >> 4, j8 = (i & 15) << 3;
                *(uint4*)(dstl + (size_t)n * CI + j8) =
                    *(const uint4*)(ps + OFF_U + (n * PS + j8) * 2);
            }
        } else {
            float* dst = ((p == 1) ? g_Tphi : g_Tg) + ((size_t)b * NSP + nb) * CI;
#pragma unroll
            for (int t = 0; t < 16; t++) {
                const int n = t * 8 + (lane & 3) * 2;
                *(float*)(ps + OFF_U + (n * PF + j0) * 4)       = D[t][0] + bias0;
                *(float*)(ps + OFF_U + ((n + 1) * PF + j0) * 4) = D[t][1] + bias0;
                *(float*)(ps + OFF_U + (n * PF + j1) * 4)       = D[t][2] + bias1;
                *(float*)(ps + OFF_U + ((n + 1) * PF + j1) * 4) = D[t][3] + bias1;
            }
            __syncthreads();
            for (int i = tid; i < 128 * 32; i += 256) {
                const int n = i >> 5, j4 = (i & 31) << 2;
                *(float4*)(dst + (size_t)n * CI + j4) =
                    *(const float4*)(ps + OFF_U + (n * PF + j4) * 4);
            }
        }
        __syncthreads();   // staging free before next projection's prefetch
    }
}

// ============================================================
// Kernel 2: 2x2 maxpool of phi/g -> bf16 hi/lo K and V, both (m, ci)
// ============================================================
__global__ void pool_kernel()
{
    const int bm = blockIdx.x;
    const int b = bm / MSP, m = bm % MSP;
    const int t = m / 196, rem = m % 196;
    const int h2 = rem / 14, w2 = rem % 14;
    const int n0 = t * 784 + (2 * h2) * 28 + 2 * w2;
    const int ci = threadIdx.x;
    const size_t base = (size_t)b * NSP * CI;
    const size_t o = ((size_t)b * MSP + m) * CI + ci;

    const float* p = g_Tphi;
    float pv = fmaxf(fmaxf(p[base + (size_t)n0 * CI + ci],
                           p[base + (size_t)(n0 + 1) * CI + ci]),
                     fmaxf(p[base + (size_t)(n0 + 28) * CI + ci],
                           p[base + (size_t)(n0 + 29) * CI + ci]));
    {
        __nv_bfloat16 h = __float2bfloat16(pv);
        g_Kh[o] = h;
        g_Kl[o] = __float2bfloat16(pv - __bfloat162float(h));
    }

    const float* gg = g_Tg;
    float gv = fmaxf(fmaxf(gg[base + (size_t)n0 * CI + ci],
                           gg[base + (size_t)(n0 + 1) * CI + ci]),
                     fmaxf(gg[base + (size_t)(n0 + 28) * CI + ci],
                           gg[base + (size_t)(n0 + 29) * CI + ci]));
    {
        __nv_bfloat16 h = __float2bfloat16(gv);
        g_Vh[o] = h;
        g_Vl[o] = __float2bfloat16(gv - __bfloat162float(h));
    }
}

// ============================================================
// Kernel 3: mma.sync flash attention, 2 CTAs/SM.
// Round 9: Q fragments register-resident; term-grouped mma issue (acc gap 4);
// deferred O rescale. grid (98, 8), 128 threads.
// SMEM: Qh/Ql (34816) + 2 KV buffers (2x34816) = 104448 -> 2 CTAs/SM.
// ============================================================
#define PQ 136
#define QT    17408          // 64*136*2
#define KT    8704           // 32*136*2
#define KVOFF 34816
#define KVB   34816
#define ATTN_SMEM (34816 + 2 * 34816)   // 104448
#define NCH 49               // 1568 / 32 exactly

__global__ __launch_bounds__(128, 2) void attn_kernel()
{
    extern __shared__ __align__(16) char smem[];
    const int tid = threadIdx.x, lane = tid & 31, warp = tid >> 5;
    const int qb = blockIdx.x * 64, b = blockIdx.y;
    const uint32_t sb = smem_u32(smem);

    const __nv_bfloat16* bKh = g_Kh + (size_t)b * MSP * CI;
    const __nv_bfloat16* bKl = g_Kl + (size_t)b * MSP * CI;
    const __nv_bfloat16* bVh = g_Vh + (size_t)b * MSP * CI;
    const __nv_bfloat16* bVl = g_Vl + (size_t)b * MSP * CI;

    // ---- issue chunk 0 (4 tiles x 32 rows x 16 segments) ----
    {
        const uint32_t bo = sb + KVOFF;
        for (int i = tid; i < 2048; i += 128) {
            const int t = i >> 9, r = (i >> 4) & 31, s = i & 15;
            const __nv_bfloat16* src =
                ((t == 0) ? bKh : (t == 1) ? bKl : (t == 2) ? bVh : bVl)
                + (size_t)r * CI + s * 8;
            CP_ASYNC16(bo + t * KT + r * 272 + s * 16, src);
        }
        CP_COMMIT();
    }

    // ---- load Q tiles to smem ----
    {
        const __nv_bfloat16* gqh = g_Qh + ((size_t)b * NSP + qb) * CI;
        const __nv_bfloat16* gql = g_Ql + ((size_t)b * NSP + qb) * CI;
        for (int i = tid; i < 64 * 16; i += 128) {
            const int r = i >> 4, c8 = (i & 15) << 3;
            *(uint4*)(smem + (r * PQ + c8) * 2) =
                *(const uint4*)(gqh + (size_t)r * CI + c8);
            *(uint4*)(smem + QT + (r * PQ + c8) * 2) =
                *(const uint4*)(gql + (size_t)r * CI + c8);
        }
    }
    __syncthreads();

    // ---- Q fragments register-resident (preloaded once) ----
    const uint32_t aQH = sb + ((warp * 16 + (lane & 15)) * PQ + ((lane >> 4) << 3)) * 2;
    const uint32_t aQL = aQH + QT;
    uint32_t QH[8][4], QL[8][4];
#pragma unroll
    for (int kk = 0; kk < 8; kk++) {
        ldsm4(QH[kk], aQH + kk * 32);
        ldsm4(QL[kk], aQL + kk * 32);
    }

    const uint32_t kRow = (lane & 7) + ((lane >> 4) << 3);
    const uint32_t kOffB = (kRow * PQ + (((lane >> 3) & 1) << 3)) * 2;
    const uint32_t vRow = (lane & 7) + (((lane >> 3) & 1) << 3);
    const uint32_t vOffB = (vRow * PQ + ((lane >> 4) << 3)) * 2;

    float O[16][4];
#pragma unroll
    for (int t = 0; t < 16; t++)
#pragma unroll
        for (int j = 0; j < 4; j++) O[t][j] = 0.f;
    float m0 = -1e30f, m1 = -1e30f, l0 = 0.f, l1 = 0.f;

    for (int kt = 0; kt < NCH; kt++) {
        if (kt + 1 < NCH) {
            const int kvb1 = (kt + 1) * 32;
            const uint32_t bo = sb + KVOFF + ((kt + 1) & 1) * KVB;
            for (int i = tid; i < 2048; i += 128) {
                const int t = i >> 9, r = (i >> 4) & 31, s = i & 15;
                const __nv_bfloat16* src =
                    ((t == 0) ? bKh : (t == 1) ? bKl : (t == 2) ? bVh : bVl)
                    + (size_t)(kvb1 + r) * CI + s * 8;
                CP_ASYNC16(bo + t * KT + r * 272 + s * 16, src);
            }
            CP_COMMIT();
            CP_WAIT1();
        } else {
            CP_WAIT0();
        }
        __syncthreads();

        const uint32_t bo = sb + KVOFF + (kt & 1) * KVB;
        const uint32_t aKH = bo + kOffB, aKL = aKH + KT;
        const uint32_t aVH = bo + 2 * KT + vOffB, aVL = aVH + KT;

        // ---- S = Qh Kh^T + Qh Kl^T + Ql Kh^T (term-grouped; acc gap 4) ----
        float S[4][4];
#pragma unroll
        for (int t = 0; t < 4; t++)
#pragma unroll
            for (int j = 0; j < 4; j++) S[t][j] = 0.f;

#pragma unroll
        for (int kk = 0; kk < 8; kk++) {
            uint32_t B0h[4], B1h[4], B0l[4], B1l[4];
            ldsm4(B0h, aKH + kk * 32);
            ldsm4(B1h, aKH + (16 * PQ * 2) + kk * 32);
            ldsm4(B0l, aKL + kk * 32);
            ldsm4(B1l, aKL + (16 * PQ * 2) + kk * 32);
            // hh
            mma16816(S[0], QH[kk], B0h[0], B0h[1]);
            mma16816(S[1], QH[kk], B0h[2], B0h[3]);
            mma16816(S[2], QH[kk], B1h[0], B1h[1]);
            mma16816(S[3], QH[kk], B1h[2], B1h[3]);
            // hl
            mma16816(S[0], QH[kk], B0l[0], B0l[1]);
            mma16816(S[1], QH[kk], B0l[2], B0l[3]);
            mma16816(S[2], QH[kk], B1l[0], B1l[1]);
            mma16816(S[3], QH[kk], B1l[2], B1l[3]);
            // lh
            mma16816(S[0], QL[kk], B0h[0], B0h[1]);
            mma16816(S[1], QL[kk], B0h[2], B0h[3]);
            mma16816(S[2], QL[kk], B1h[0], B1h[1]);
            mma16816(S[3], QL[kk], B1h[2], B1h[3]);
        }

        // ---- online softmax (1568 = 49*32 exactly; no tail mask) ----
        float mx0 = -1e30f, mx1 = -1e30f;
#pragma unroll
        for (int t = 0; t < 4; t++) {
            mx0 = fmaxf(mx0, fmaxf(S[t][0], S[t][1]));
            mx1 = fmaxf(mx1, fmaxf(S[t][2], S[t][3]));
        }
        mx0 = fmaxf(mx0, __shfl_xor_sync(0xffffffffu, mx0, 1));
        mx0 = fmaxf(mx0, __shfl_xor_sync(0xffffffffu, mx0, 2));
        mx1 = fmaxf(mx1, __shfl_xor_sync(0xffffffffu, mx1, 1));
        mx1 = fmaxf(mx1, __shfl_xor_sync(0xffffffffu, mx1, 2));
        const float mn0 = fmaxf(m0, mx0), mn1 = fmaxf(m1, mx1);
        const float f0 = __expf(m0 - mn0), f1 = __expf(m1 - mn1);
        m0 = mn0; m1 = mn1;
        float s0 = 0.f, s1 = 0.f;
#pragma unroll
        for (int t = 0; t < 4; t++) {
            S[t][0] = __expf(S[t][0] - mn0); s0 += S[t][0];
            S[t][1] = __expf(S[t][1] - mn0); s0 += S[t][1];
            S[t][2] = __expf(S[t][2] - mn1); s1 += S[t][2];
            S[t][3] = __expf(S[t][3] - mn1); s1 += S[t][3];
        }
        s0 += __shfl_xor_sync(0xffffffffu, s0, 1);
        s0 += __shfl_xor_sync(0xffffffffu, s0, 2);
        s1 += __shfl_xor_sync(0xffffffffu, s1, 1);
        s1 += __shfl_xor_sync(0xffffffffu, s1, 2);
        l0 = l0 * f0 + s0;
        l1 = l1 * f1 + s1;

        // ---- deferred O rescale: skip when no row max moved in this warp ----
        if (__any_sync(0xffffffffu, (f0 != 1.f) | (f1 != 1.f))) {
#pragma unroll
            for (int t = 0; t < 16; t++) {
                O[t][0] *= f0; O[t][1] *= f0; O[t][2] *= f1; O[t][3] *= f1;
            }
        }

        // ---- P -> bf16 hi/lo A-fragments (2 k16 steps) ----
        uint32_t Ph[2][4], Pl[2][4];
#pragma unroll
        for (int kk = 0; kk < 2; kk++) {
            const int t0 = 2 * kk, t1 = 2 * kk + 1;
#pragma unroll
            for (int q = 0; q < 4; q++) {
                const int tt = (q < 2) ? t0 : t1;
                const int jj = (q & 1) * 2;
                const float p0 = S[tt][jj], p1 = S[tt][jj + 1];
                __nv_bfloat162 h2 = __floats2bfloat162_rn(p0, p1);
                Ph[kk][q] = *(uint32_t*)&h2;
                __nv_bfloat162 l2 = __floats2bfloat162_rn(
                    p0 - __bfloat162float(h2.x), p1 - __bfloat162float(h2.y));
                Pl[kk][q] = *(uint32_t*)&l2;
            }
        }

        // ---- O += Ph Vh + Ph Vl + Pl Vh (g-pairs; term-grouped; acc gap 4) ----
#pragma unroll
        for (int kk = 0; kk < 2; kk++) {
#pragma unroll
            for (int gp = 0; gp < 4; gp++) {
                const int ga = 2 * gp, gb2 = 2 * gp + 1;
                uint32_t VhA[4], VhB[4], VlA[4], VlB[4];
                ldsm4t(VhA, aVH + kk * (16 * PQ * 2) + ga * 32);
                ldsm4t(VhB, aVH + kk * (16 * PQ * 2) + gb2 * 32);
                ldsm4t(VlA, aVL + kk * (16 * PQ * 2) + ga * 32);
                ldsm4t(VlB, aVL + kk * (16 * PQ * 2) + gb2 * 32);
                // hh
                mma16816(O[2 * ga],      Ph[kk], VhA[0], VhA[1]);
                mma16816(O[2 * ga + 1],  Ph[kk], VhA[2], VhA[3]);
                mma16816(O[2 * gb2],     Ph[kk], VhB[0], VhB[1]);
                mma16816(O[2 * gb2 + 1], Ph[kk], VhB[2], VhB[3]);
                // hl
                mma16816(O[2 * ga],      Ph[kk], VlA[0], VlA[1]);
                mma16816(O[2 * ga + 1],  Ph[kk], VlA[2], VlA[3]);
                mma16816(O[2 * gb2],     Ph[kk], VlB[0], VlB[1]);
                mma16816(O[2 * gb2 + 1], Ph[kk], VlB[2], VlB[3]);
                // lh
                mma16816(O[2 * ga],      Pl[kk], VhA[0], VhA[1]);
                mma16816(O[2 * ga + 1],  Pl[kk], VhA[2], VhA[3]);
                mma16816(O[2 * gb2],     Pl[kk], VhB[0], VhB[1]);
                mma16816(O[2 * gb2 + 1], Pl[kk], VhB[2], VhB[3]);
            }
        }
        __syncthreads();
    }

    // ---- y = O / l, pre-split bf16 hi/lo ----
    {
        const float inv0 = 1.0f / l0, inv1 = 1.0f / l1;
        const int r0 = qb + warp * 16 + (lane >> 2);
        const size_t base0 = ((size_t)b * NSP + r0) * CI + (lane & 3) * 2;
        const size_t base1 = base0 + 8 * CI;
#pragma unroll
        for (int t = 0; t < 16; t++) {
            const float v0 = O[t][0] * inv0, v1 = O[t][1] * inv0;
            __nv_bfloat162 h = __floats2bfloat162_rn(v0, v1);
            *(__nv_bfloat162*)(g_Yh + base0 + t * 8) = h;
            *(__nv_bfloat162*)(g_Yl + base0 + t * 8) = __floats2bfloat162_rn(
                v0 - __bfloat162float(h.x), v1 - __bfloat162float(h.y));
            const float w0 = O[t][2] * inv1, w1 = O[t][3] * inv1;
            __nv_bfloat162 h2 = __floats2bfloat162_rn(w0, w1);
            *(__nv_bfloat162*)(g_Yh + base1 + t * 8) = h2;
            *(__nv_bfloat162*)(g_Yl + base1 + t * 8) = __floats2bfloat162_rn(
                w0 - __bfloat162float(h2.x), w1 - __bfloat162float(h2.y));
        }
    }
}

// ============================================================
// Kernel 4: out = W*y + b + x, co=128 x n=64 tiles, 2 CTAs/SM, cp.async.
// grid (98, 2, 8), 256 threads.
// ============================================================
#define OW_WL 34816
#define OW_YH 69632
#define OW_YL 87040
#define OUT_SMEM 104448

__global__ __launch_bounds__(256) void out_kernel(
    const float* __restrict__ x, const float* __restrict__ Wb,
    float* __restrict__ out)
{
    extern __shared__ __align__(16) char ps[];
    const int tid = threadIdx.x, lane = tid & 31, warp = tid >> 5;
    const int nb = blockIdx.x * 64, co0 = blockIdx.y * 128, b = blockIdx.z;
    const uint32_t sb = smem_u32(ps);

    // cp.async W (pre-split) and Y tiles
    for (int i = tid; i < 2048; i += 256) {
        const int co = i >> 4, s = i & 15;
        const size_t gsrc = (size_t)(co0 + co) * CI + s * 8;
        CP_ASYNC16(sb + co * 272 + s * 16,         g_OWh + gsrc);
        CP_ASYNC16(sb + OW_WL + co * 272 + s * 16, g_OWl + gsrc);
    }
    {
        const __nv_bfloat16* yh = g_Yh + ((size_t)b * NSP + nb) * CI;
        const __nv_bfloat16* yl = g_Yl + ((size_t)b * NSP + nb) * CI;
        for (int i = tid; i < 1024; i += 256) {
            const int n = i >> 4, s = i & 15;
            const size_t gsrc = (size_t)n * CI + s * 8;
            CP_ASYNC16(sb + OW_YH + n * 272 + s * 16, yh + gsrc);
            CP_ASYNC16(sb + OW_YL + n * 272 + s * 16, yl + gsrc);
        }
    }
    CP_COMMIT();
    CP_WAIT0();
    __syncthreads();

    float D[8][4];
#pragma unroll
    for (int t = 0; t < 8; t++)
#pragma unroll
        for (int j = 0; j < 4; j++) D[t][j] = 0.f;

    const uint32_t aW = sb + ((warp * 16 + (lane & 15)) * 136 + ((lane >> 4) << 3)) * 2;
    const uint32_t kRow = (lane & 7) + ((lane >> 4) << 3);
    const uint32_t aY = sb + OW_YH + (kRow * 136 + (((lane >> 3) & 1) << 3)) * 2;

#pragma unroll
    for (int kk = 0; kk < 8; kk++) {
        uint32_t Ah[4], Al[4];
        ldsm4(Ah, aW + kk * 32);
        ldsm4(Al, aW + OW_WL + kk * 32);
#pragma unroll
        for (int g = 0; g < 4; g++) {
            uint32_t Bh[4], Bl[4];
            ldsm4(Bh, aY + g * (16 * 136 * 2) + kk * 32);
            ldsm4(Bl, aY + (OW_YL - OW_YH) + g * (16 * 136 * 2) + kk * 32);
            mma16816(D[2 * g],     Ah, Bh[0], Bh[1]);
            mma16816(D[2 * g + 1], Ah, Bh[2], Bh[3]);
            mma16816(D[2 * g],     Ah, Bl[0], Bl[1]);
            mma16816(D[2 * g + 1], Ah, Bl[2], Bl[3]);
            mma16816(D[2 * g],     Al, Bh[0], Bh[1]);
            mma16816(D[2 * g + 1], Al, Bh[2], Bh[3]);
        }
    }

    const int co = co0 + warp * 16 + (lane >> 2);
    const float bias0 = Wb[co], bias1 = Wb[co + 8];
    const float* xr0 = x + ((size_t)b * CIN + co) * NSP + nb;
    const float* xr1 = xr0 + (size_t)8 * NSP;
    float* o0 = out + ((size_t)b * CIN + co) * NSP + nb;
    float* o1 = o0 + (size_t)8 * NSP;
#pragma unroll
    for (int t = 0; t < 8; t++) {
        const int n = t * 8 + (lane & 3) * 2;
        const float2 xv0 = *(const float2*)(xr0 + n);
        *(float2*)(o0 + n) = make_float2(D[t][0] + bias0 + xv0.x,
                                         D[t][1] + bias0 + xv0.y);
        const float2 xv1 = *(const float2*)(xr1 + n);
        *(float2*)(o1 + n) = make_float2(D[t][2] + bias1 + xv1.x,
                                         D[t][3] + bias1 + xv1.y);
    }
}

// ============================================================
extern "C" void kernel_launch(void* const* d_in, const int* in_sizes, int n_in,
                              void* d_out, int out_size)
{
    const float* x    = (const float*)d_in[0];
    const float* g_w  = (const float*)d_in[1];
    const float* g_b  = (const float*)d_in[2];
    const float* th_w = (const float*)d_in[3];
    const float* th_b = (const float*)d_in[4];
    const float* ph_w = (const float*)d_in[5];
    const float* ph_b = (const float*)d_in[6];
    const float* W_w  = (const float*)d_in[7];
    const float* W_b  = (const float*)d_in[8];
    float* out = (float*)d_out;

    cudaFuncSetAttribute(proj_kernel,
                         cudaFuncAttributeMaxDynamicSharedMemorySize, PROJ_SMEM);
    cudaFuncSetAttribute(attn_kernel,
                         cudaFuncAttributeMaxDynamicSharedMemorySize, ATTN_SMEM);
    cudaFuncSetAttribute(out_kernel,
                         cudaFuncAttributeMaxDynamicSharedMemorySize, OUT_SMEM);

    prep_kernel<<<512, 256>>>(th_w, ph_w, g_w, W_w);

    dim3 g1(NSP / 128, BATCH);
    proj_kernel<<<g1, 256, PROJ_SMEM>>>(x, th_b, ph_b, g_b);

    pool_kernel<<<BATCH * MSP, 128>>>();

    dim3 g2(NSP / 64, BATCH);
    attn_kernel<<<g2, 128, ATTN_SMEM>>>();

    dim3 g3(NSP / 64, CIN / 128, BATCH);
    out_kernel<<<g3, 256, OUT_SMEM>>>(x, W_b, out);
}